// round 1
// baseline (speedup 1.0000x reference)
#include <cuda_runtime.h>
#include <cuda_bf16.h>

#define EPS 1e-5f
#define WARPS 8
#define THREADS 256

__global__ __launch_bounds__(THREADS) void attn_agg_kernel(
    const float* __restrict__ x, const float* __restrict__ mask,
    const float* __restrict__ attn_w, const float* __restrict__ attn_b,
    const float* __restrict__ w1, const float* __restrict__ b1,
    const float* __restrict__ g1, const float* __restrict__ be1,
    const float* __restrict__ m1, const float* __restrict__ v1,
    const float* __restrict__ w2, const float* __restrict__ b2,
    const float* __restrict__ g2, const float* __restrict__ be2,
    const float* __restrict__ m2, const float* __restrict__ v2,
    const float* __restrict__ w3, const float* __restrict__ b3,
    float* __restrict__ out, int B, int write_weight, int write_cls)
{
    // ---- shared: all small weights + folded BN constants + per-warp h1 ----
    __shared__ float4 s_aw[64];          // attn_w as float4 (256 floats)
    __shared__ float  s_w1t[4][128];     // w1 transposed: [n][j]
    __shared__ float  s_b1[128], s_a1[128], s_c1[128];
    __shared__ float4 s_w2q[64][33];     // w2 rows as float4, padded (conflict-free)
    __shared__ float  s_b2[64], s_a2[64], s_c2[64];
    __shared__ float  s_w3[2][64];
    __shared__ float  s_b3[2], s_ab;
    __shared__ float4 s_h1[WARPS][32];   // per-warp h1 (128 floats)

    const int tid = threadIdx.x;

    for (int i = tid; i < 64; i += THREADS)
        s_aw[i] = ((const float4*)attn_w)[i];
    for (int i = tid; i < 512; i += THREADS)
        s_w1t[i & 3][i >> 2] = w1[(i >> 2) * 4 + (i & 3)];
    for (int i = tid; i < 128; i += THREADS) {
        float a = g1[i] * rsqrtf(v1[i] + EPS);
        s_a1[i] = a; s_c1[i] = be1[i] - a * m1[i]; s_b1[i] = b1[i];
    }
    for (int i = tid; i < 64 * 32; i += THREADS) {
        int j = i >> 5, kk = i & 31;
        s_w2q[j][kk] = ((const float4*)w2)[j * 32 + kk];
    }
    for (int i = tid; i < 64; i += THREADS) {
        float a = g2[i] * rsqrtf(v2[i] + EPS);
        s_a2[i] = a; s_c2[i] = be2[i] - a * m2[i]; s_b2[i] = b2[i];
    }
    for (int i = tid; i < 128; i += THREADS)
        s_w3[i >> 6][i & 63] = w3[i];
    if (tid == 0) { s_b3[0] = b3[0]; s_b3[1] = b3[1]; s_ab = attn_b[0]; }
    __syncthreads();

    const int warp = tid >> 5, lane = tid & 31;
    const float4 wa = s_aw[lane], wb = s_aw[32 + lane];
    float* h1p = (float*)s_h1[warp];

    for (long long b = (long long)blockIdx.x * WARPS + warp; b < B;
         b += (long long)gridDim.x * WARPS) {
        // ---- load full x row into registers: 8 coalesced float4 per lane ----
        const float4* xr = (const float4*)(x + (size_t)b * 1024);
        float4 xa0 = xr[lane],        xb0 = xr[32 + lane];
        float4 xa1 = xr[64 + lane],   xb1 = xr[96 + lane];
        float4 xa2 = xr[128 + lane],  xb2 = xr[160 + lane];
        float4 xa3 = xr[192 + lane],  xb3 = xr[224 + lane];

        // ---- attention dots (4 parallel warp reductions) ----
        float s0 = xa0.x*wa.x + xa0.y*wa.y + xa0.z*wa.z + xa0.w*wa.w
                 + xb0.x*wb.x + xb0.y*wb.y + xb0.z*wb.z + xb0.w*wb.w;
        float s1 = xa1.x*wa.x + xa1.y*wa.y + xa1.z*wa.z + xa1.w*wa.w
                 + xb1.x*wb.x + xb1.y*wb.y + xb1.z*wb.z + xb1.w*wb.w;
        float s2 = xa2.x*wa.x + xa2.y*wa.y + xa2.z*wa.z + xa2.w*wa.w
                 + xb2.x*wb.x + xb2.y*wb.y + xb2.z*wb.z + xb2.w*wb.w;
        float s3 = xa3.x*wa.x + xa3.y*wa.y + xa3.z*wa.z + xa3.w*wa.w
                 + xb3.x*wb.x + xb3.y*wb.y + xb3.z*wb.z + xb3.w*wb.w;
        #pragma unroll
        for (int o = 16; o; o >>= 1) {
            s0 += __shfl_xor_sync(0xFFFFFFFFu, s0, o);
            s1 += __shfl_xor_sync(0xFFFFFFFFu, s1, o);
            s2 += __shfl_xor_sync(0xFFFFFFFFu, s2, o);
            s3 += __shfl_xor_sync(0xFFFFFFFFu, s3, o);
        }

        const float ab = s_ab;
        const float4 mk = ((const float4*)mask)[b];
        float t0 = tanhf(s0 + ab) + mk.x;
        float t1 = tanhf(s1 + ab) + mk.y;
        float t2 = tanhf(s2 + ab) + mk.z;
        float t3 = tanhf(s3 + ab) + mk.w;

        // argmax over members (first occurrence)
        int mi = 0; float bm = t0;
        if (t1 > bm) { bm = t1; mi = 1; }
        if (t2 > bm) { bm = t2; mi = 2; }
        if (t3 > bm) { bm = t3; mi = 3; }

        // stable softmax over 4 members
        float mx = fmaxf(fmaxf(t0, t1), fmaxf(t2, t3));
        float e0 = __expf(t0 - mx), e1 = __expf(t1 - mx);
        float e2 = __expf(t2 - mx), e3 = __expf(t3 - mx);
        float inv = 1.0f / (e0 + e1 + e2 + e3);
        float wt0 = e0 * inv, wt1 = e1 * inv, wt2 = e2 * inv, wt3 = e3 * inv;

        // ---- MLP layer 1: 4 units per lane -> warp-shared h1 ----
        #pragma unroll
        for (int u = 0; u < 4; u++) {
            int j = lane + u * 32;
            float z = wt0 * s_w1t[0][j] + wt1 * s_w1t[1][j]
                    + wt2 * s_w1t[2][j] + wt3 * s_w1t[3][j] + s_b1[j];
            z = fmaxf(z, 0.0f);
            h1p[j] = s_a1[j] * z + s_c1[j];
        }
        __syncwarp();

        // ---- MLP layer 2: 2 units per lane, float4 LDS inner loop ----
        float acc0 = s_b2[lane], acc1 = s_b2[lane + 32];
        #pragma unroll 8
        for (int kk = 0; kk < 32; kk++) {
            float4 h  = s_h1[warp][kk];          // broadcast
            float4 u0 = s_w2q[lane][kk];         // conflict-free (pad 33)
            float4 u1 = s_w2q[lane + 32][kk];
            acc0 += h.x*u0.x + h.y*u0.y + h.z*u0.z + h.w*u0.w;
            acc1 += h.x*u1.x + h.y*u1.y + h.z*u1.z + h.w*u1.w;
        }
        __syncwarp();   // protect s_h1 before next row's writes
        float h20 = s_a2[lane]      * fmaxf(acc0, 0.0f) + s_c2[lane];
        float h21 = s_a2[lane + 32] * fmaxf(acc1, 0.0f) + s_c2[lane + 32];

        // ---- logits (warp reduction) ----
        float z0 = h20 * s_w3[0][lane] + h21 * s_w3[0][lane + 32];
        float z1 = h20 * s_w3[1][lane] + h21 * s_w3[1][lane + 32];
        #pragma unroll
        for (int o = 16; o; o >>= 1) {
            z0 += __shfl_xor_sync(0xFFFFFFFFu, z0, o);
            z1 += __shfl_xor_sync(0xFFFFFFFFu, z1, o);
        }
        z0 += s_b3[0]; z1 += s_b3[1];
        float zm = fmaxf(z0, z1);
        float p0 = __expf(z0 - zm), p1 = __expf(z1 - zm);
        float inv2 = 1.0f / (p0 + p1);
        p0 *= inv2; p1 = p1 * inv2 - 0.5f;
        const bool cls1 = (p1 > p0);

        // ---- conditional pooling ----
        float4 ga = (mi == 0) ? xa0 : (mi == 1) ? xa1 : (mi == 2) ? xa2 : xa3;
        float4 gb = (mi == 0) ? xb0 : (mi == 1) ? xb1 : (mi == 2) ? xb2 : xb3;
        float4 pa, pb;
        pa.x = wt0*xa0.x + wt1*xa1.x + wt2*xa2.x + wt3*xa3.x;
        pa.y = wt0*xa0.y + wt1*xa1.y + wt2*xa2.y + wt3*xa3.y;
        pa.z = wt0*xa0.z + wt1*xa1.z + wt2*xa2.z + wt3*xa3.z;
        pa.w = wt0*xa0.w + wt1*xa1.w + wt2*xa2.w + wt3*xa3.w;
        pb.x = wt0*xb0.x + wt1*xb1.x + wt2*xb2.x + wt3*xb3.x;
        pb.y = wt0*xb0.y + wt1*xb1.y + wt2*xb2.y + wt3*xb3.y;
        pb.z = wt0*xb0.z + wt1*xb1.z + wt2*xb2.z + wt3*xb3.z;
        pb.w = wt0*xb0.w + wt1*xb1.w + wt2*xb2.w + wt3*xb3.w;
        float4 ra = cls1 ? ga : pa;
        float4 rb = cls1 ? gb : pb;

        float4* orow = (float4*)(out + (size_t)b * 256);
        orow[lane]      = ra;
        orow[32 + lane] = rb;

        if (write_weight && lane < 4) {
            float wv = (lane == 0) ? wt0 : (lane == 1) ? wt1 : (lane == 2) ? wt2 : wt3;
            out[(size_t)B * 256 + (size_t)b * 4 + lane] = wv;
        }
        if (write_cls && lane == 0)
            out[(size_t)B * 260 + b] = cls1 ? 1.0f : 0.0f;
    }
}

extern "C" void kernel_launch(void* const* d_in, const int* in_sizes, int n_in,
                              void* d_out, int out_size)
{
    const float* x      = (const float*)d_in[0];
    const float* mask   = (const float*)d_in[1];
    const float* attn_w = (const float*)d_in[2];
    const float* attn_b = (const float*)d_in[3];
    const float* w1     = (const float*)d_in[4];
    const float* b1     = (const float*)d_in[5];
    const float* g1     = (const float*)d_in[6];
    const float* be1    = (const float*)d_in[7];
    const float* m1     = (const float*)d_in[8];
    const float* v1     = (const float*)d_in[9];
    const float* w2     = (const float*)d_in[10];
    const float* b2     = (const float*)d_in[11];
    const float* g2     = (const float*)d_in[12];
    const float* be2    = (const float*)d_in[13];
    const float* m2     = (const float*)d_in[14];
    const float* v2     = (const float*)d_in[15];
    const float* w3     = (const float*)d_in[16];
    const float* b3     = (const float*)d_in[17];
    float* out = (float*)d_out;

    const int B = in_sizes[0] / 1024;   // x = [B,4,256]
    // Output assumed flattened tuple concat [ret | weight | cls], gated on size
    const long long need_w = (long long)B * 260;
    const long long need_c = (long long)B * 261;
    const int write_weight = ((long long)out_size >= need_w) ? 1 : 0;
    const int write_cls    = ((long long)out_size >= need_c) ? 1 : 0;

    dim3 grid(1184), block(THREADS);
    attn_agg_kernel<<<grid, block>>>(x, mask, attn_w, attn_b,
                                     w1, b1, g1, be1, m1, v1,
                                     w2, b2, g2, be2, m2, v2,
                                     w3, b3, out, B, write_weight, write_cls);
}

// round 2
// speedup vs baseline: 1.0292x; 1.0292x over previous
#include <cuda_runtime.h>
#include <cuda_bf16.h>

#define EPS 1e-5f
#define LN3 1.0986122886681098f
#define WARPS 4
#define THREADS 128
#define GRID 2048

// ---- precomputed classifier constants (prep kernel -> device globals) ----
__device__ __align__(16) float g_M[128 * 64];   // k-major: g_M[k*64+j] = w2[j][k]*a1[k]
__device__ __align__(16) float g_w1p[128 * 4];  // w1 row-major copy: [k][n]
__device__ __align__(16) float g_b1[128];
__device__ __align__(16) float g_q[64];         // w2@c1 + b2
__device__ __align__(16) float g_e[64];         // (w3[1]-w3[0]) * a2
__device__ float g_C[1];                        // sum((w3[1]-w3[0])*c2) + (b3[1]-b3[0])

__global__ void prep_kernel(
    const float* __restrict__ w1, const float* __restrict__ b1,
    const float* __restrict__ g1, const float* __restrict__ be1,
    const float* __restrict__ m1, const float* __restrict__ v1,
    const float* __restrict__ w2, const float* __restrict__ b2,
    const float* __restrict__ g2, const float* __restrict__ be2,
    const float* __restrict__ m2, const float* __restrict__ v2,
    const float* __restrict__ w3, const float* __restrict__ b3)
{
    __shared__ float a1[128], c1[128];
    int t = threadIdx.x;  // 128 threads
    {
        float a = g1[t] * rsqrtf(v1[t] + EPS);
        a1[t] = a; c1[t] = be1[t] - a * m1[t];
        g_b1[t] = b1[t];
        #pragma unroll
        for (int n = 0; n < 4; n++) g_w1p[t * 4 + n] = w1[t * 4 + n];
    }
    __syncthreads();
    for (int i = t; i < 128 * 64; i += 128) {
        int j = i >> 7, k = i & 127;
        g_M[k * 64 + j] = w2[j * 128 + k] * a1[k];
    }
    if (t < 64) {
        float acc = b2[t];
        #pragma unroll 8
        for (int k = 0; k < 128; k++) acc += w2[t * 128 + k] * c1[k];
        g_q[t] = acc;
        float a2 = g2[t] * rsqrtf(v2[t] + EPS);
        g_e[t] = (w3[64 + t] - w3[t]) * a2;
    }
    if (t == 0) {
        float C = b3[1] - b3[0];
        for (int j = 0; j < 64; j++) {
            float a2 = g2[j] * rsqrtf(v2[j] + EPS);
            float c2 = be2[j] - a2 * m2[j];
            C += (w3[64 + j] - w3[j]) * c2;
        }
        g_C[0] = C;
    }
}

__device__ __forceinline__ unsigned long long ffma2(
    unsigned long long a, unsigned long long b, unsigned long long c)
{
    unsigned long long d;
    asm("fma.rn.f32x2 %0, %1, %2, %3;" : "=l"(d) : "l"(a), "l"(b), "l"(c));
    return d;
}

__global__ __launch_bounds__(THREADS, 4) void attn_agg_kernel(
    const float* __restrict__ x, const float* __restrict__ mask,
    const float* __restrict__ attn_w, const float* __restrict__ attn_b,
    float* __restrict__ out, int B, int write_weight, int write_cls)
{
    __shared__ float4 s_M4[128 * 16];   // 32KB, k-major columns of M (j-quads)
    __shared__ float4 s_w1p[128];       // 2KB
    __shared__ float  s_b1[128];
    __shared__ float4 s_aw[64];         // 1KB
    __shared__ float  s_q[64], s_e[64];
    __shared__ float  s_C, s_ab;

    const int tid = threadIdx.x;
    for (int i = tid; i < 2048; i += THREADS) s_M4[i] = ((const float4*)g_M)[i];
    for (int i = tid; i < 128; i += THREADS) {
        s_w1p[i] = ((const float4*)g_w1p)[i];
        s_b1[i] = g_b1[i];
    }
    for (int i = tid; i < 64; i += THREADS) {
        s_aw[i] = ((const float4*)attn_w)[i];
        s_q[i] = g_q[i]; s_e[i] = g_e[i];
    }
    if (tid == 0) { s_C = g_C[0]; s_ab = attn_b[0]; }
    __syncthreads();

    const int warp = tid >> 5, lane = tid & 31;
    const unsigned FULL = 0xFFFFFFFFu;
    const float4 wa = s_aw[lane], wb = s_aw[32 + lane];
    const float ab = s_ab, Cc = s_C;

    const int nGroups = (B + 31) >> 5;
    const int totW = GRID * WARPS;

    for (int g = blockIdx.x * WARPS + warp; g < nGroups; g += totW) {
        const long long base = (long long)g << 5;
        const int rmax = (int)min((long long)32, (long long)B - base);
        const bool myvalid = (lane < rmax);

        // ---------------- Phase 1: warp-per-row streaming ----------------
        float mw0 = 0.f, mw1 = 0.f, mw2 = 0.f, mw3 = 0.f;
        int mmi = 0;
        for (int r = 0; r < rmax; r++) {
            const long long b = base + r;
            const float4* xr = (const float4*)(x + b * 1024);
            float4 xa0 = xr[lane],       xb0 = xr[32 + lane];
            float4 xa1 = xr[64 + lane],  xb1 = xr[96 + lane];
            float4 xa2 = xr[128 + lane], xb2 = xr[160 + lane];
            float4 xa3 = xr[192 + lane], xb3 = xr[224 + lane];

            float s0 = xa0.x*wa.x + xa0.y*wa.y + xa0.z*wa.z + xa0.w*wa.w
                     + xb0.x*wb.x + xb0.y*wb.y + xb0.z*wb.z + xb0.w*wb.w;
            float s1 = xa1.x*wa.x + xa1.y*wa.y + xa1.z*wa.z + xa1.w*wa.w
                     + xb1.x*wb.x + xb1.y*wb.y + xb1.z*wb.z + xb1.w*wb.w;
            float s2 = xa2.x*wa.x + xa2.y*wa.y + xa2.z*wa.z + xa2.w*wa.w
                     + xb2.x*wb.x + xb2.y*wb.y + xb2.z*wb.z + xb2.w*wb.w;
            float s3 = xa3.x*wa.x + xa3.y*wa.y + xa3.z*wa.z + xa3.w*wa.w
                     + xb3.x*wb.x + xb3.y*wb.y + xb3.z*wb.z + xb3.w*wb.w;
            #pragma unroll
            for (int o = 16; o; o >>= 1) {
                s0 += __shfl_xor_sync(FULL, s0, o);
                s1 += __shfl_xor_sync(FULL, s1, o);
                s2 += __shfl_xor_sync(FULL, s2, o);
                s3 += __shfl_xor_sync(FULL, s3, o);
            }

            const float4 mk = ((const float4*)mask)[b];
            float t0 = tanhf(s0 + ab) + mk.x;
            float t1 = tanhf(s1 + ab) + mk.y;
            float t2 = tanhf(s2 + ab) + mk.z;
            float t3 = tanhf(s3 + ab) + mk.w;

            int mi = 0; float bm = t0;
            if (t1 > bm) { bm = t1; mi = 1; }
            if (t2 > bm) { bm = t2; mi = 2; }
            if (t3 > bm) { bm = t3; mi = 3; }

            float mx = fmaxf(fmaxf(t0, t1), fmaxf(t2, t3));
            float e0 = __expf(t0 - mx), e1 = __expf(t1 - mx);
            float e2 = __expf(t2 - mx), e3 = __expf(t3 - mx);
            float inv = 1.0f / (e0 + e1 + e2 + e3);
            float wt0 = e0 * inv, wt1 = e1 * inv, wt2 = e2 * inv, wt3 = e3 * inv;

            // pooled (attention-weighted sum) -> streamed to out now
            float4 pa, pb;
            pa.x = wt0*xa0.x + wt1*xa1.x + wt2*xa2.x + wt3*xa3.x;
            pa.y = wt0*xa0.y + wt1*xa1.y + wt2*xa2.y + wt3*xa3.y;
            pa.z = wt0*xa0.z + wt1*xa1.z + wt2*xa2.z + wt3*xa3.z;
            pa.w = wt0*xa0.w + wt1*xa1.w + wt2*xa2.w + wt3*xa3.w;
            pb.x = wt0*xb0.x + wt1*xb1.x + wt2*xb2.x + wt3*xb3.x;
            pb.y = wt0*xb0.y + wt1*xb1.y + wt2*xb2.y + wt3*xb3.y;
            pb.z = wt0*xb0.z + wt1*xb1.z + wt2*xb2.z + wt3*xb3.z;
            pb.w = wt0*xb0.w + wt1*xb1.w + wt2*xb2.w + wt3*xb3.w;
            float4* orow = (float4*)(out + (size_t)b * 256);
            orow[lane]      = pa;
            orow[32 + lane] = pb;

            if (write_weight && lane < 4) {
                float wv = (lane == 0) ? wt0 : (lane == 1) ? wt1 : (lane == 2) ? wt2 : wt3;
                out[(size_t)B * 256 + (size_t)b * 4 + lane] = wv;
            }
            if (lane == r) { mw0 = wt0; mw1 = wt1; mw2 = wt2; mw3 = wt3; mmi = mi; }
        }

        // ------------- Phase 2: thread-per-row MLP (32 rows lockstep) -------------
        unsigned long long acc[32];
        #pragma unroll
        for (int i = 0; i < 32; i++) acc[i] = 0ull;

        const ulonglong2* Mp = (const ulonglong2*)s_M4;  // 16 per k-column
        #pragma unroll 4
        for (int k = 0; k < 128; k++) {
            float4 wp = s_w1p[k];
            float z = fmaf(mw0, wp.x, fmaf(mw1, wp.y,
                      fmaf(mw2, wp.z, fmaf(mw3, wp.w, s_b1[k]))));
            float v = fmaxf(z, 0.0f);
            unsigned long long vv;
            asm("mov.b64 %0, {%1, %1};" : "=l"(vv) : "f"(v));
            const ulonglong2* row = Mp + k * 16;
            #pragma unroll
            for (int t = 0; t < 16; t++) {
                ulonglong2 m = row[t];
                acc[2 * t]     = ffma2(m.x, vv, acc[2 * t]);
                acc[2 * t + 1] = ffma2(m.y, vv, acc[2 * t + 1]);
            }
        }

        float dec = Cc;
        #pragma unroll
        for (int i = 0; i < 32; i++) {
            float z0 = __uint_as_float((unsigned)(acc[i] & 0xFFFFFFFFull)) + s_q[2 * i];
            float z1 = __uint_as_float((unsigned)(acc[i] >> 32))           + s_q[2 * i + 1];
            dec = fmaf(s_e[2 * i],     fmaxf(z0, 0.0f), dec);
            dec = fmaf(s_e[2 * i + 1], fmaxf(z1, 0.0f), dec);
        }
        const bool cls1 = myvalid && (dec > LN3);

        // ------------- Phase 3: rare argmax-gather overwrite + cls write -------------
        unsigned mbits = __ballot_sync(FULL, cls1);
        while (mbits) {
            const int r = __ffs(mbits) - 1;
            mbits &= mbits - 1;
            const long long b = base + r;
            const int gmi = __shfl_sync(FULL, mmi, r);
            const float4* gsrc = (const float4*)(x + b * 1024 + (size_t)gmi * 256);
            float4 v0 = gsrc[lane], v1 = gsrc[32 + lane];
            float4* orow = (float4*)(out + (size_t)b * 256);
            orow[lane]      = v0;
            orow[32 + lane] = v1;
        }
        if (write_cls && myvalid)
            out[(size_t)B * 260 + base + lane] = cls1 ? 1.0f : 0.0f;
    }
}

extern "C" void kernel_launch(void* const* d_in, const int* in_sizes, int n_in,
                              void* d_out, int out_size)
{
    const float* x      = (const float*)d_in[0];
    const float* mask   = (const float*)d_in[1];
    const float* attn_w = (const float*)d_in[2];
    const float* attn_b = (const float*)d_in[3];
    const float* w1     = (const float*)d_in[4];
    const float* b1     = (const float*)d_in[5];
    const float* g1     = (const float*)d_in[6];
    const float* be1    = (const float*)d_in[7];
    const float* m1     = (const float*)d_in[8];
    const float* v1     = (const float*)d_in[9];
    const float* w2     = (const float*)d_in[10];
    const float* b2     = (const float*)d_in[11];
    const float* g2     = (const float*)d_in[12];
    const float* be2    = (const float*)d_in[13];
    const float* m2     = (const float*)d_in[14];
    const float* v2     = (const float*)d_in[15];
    const float* w3     = (const float*)d_in[16];
    const float* b3     = (const float*)d_in[17];
    float* out = (float*)d_out;

    const int B = in_sizes[0] / 1024;   // x = [B,4,256]
    const long long need_w = (long long)B * 260;
    const long long need_c = (long long)B * 261;
    const int write_weight = ((long long)out_size >= need_w) ? 1 : 0;
    const int write_cls    = ((long long)out_size >= need_c) ? 1 : 0;

    prep_kernel<<<1, 128>>>(w1, b1, g1, be1, m1, v1,
                            w2, b2, g2, be2, m2, v2, w3, b3);
    attn_agg_kernel<<<GRID, THREADS>>>(x, mask, attn_w, attn_b,
                                       out, B, write_weight, write_cls);
}

// round 4
// speedup vs baseline: 1.3387x; 1.3007x over previous
#include <cuda_runtime.h>
#include <cuda_bf16.h>

#define EPS 1e-5f
#define LN3 1.0986122886681098f

// ---- static scratch + precomputed classifier constants ----
__device__ __align__(16) float4 g_wt[1 << 19];  // per-row softmax weights
__device__ __align__(16) float g_M[128 * 64];   // k-major: g_M[k*64+j] = w2[j][k]*a1[k]
__device__ __align__(16) float g_w1p[128 * 4];  // w1 row-major: [k][n]
__device__ __align__(16) float g_b1[128];
__device__ __align__(16) float g_q[64];         // w2@c1 + b2
__device__ __align__(16) float g_e[64];         // (w3[1]-w3[0]) * a2
__device__ float g_C[1];                        // Σ w3diff*c2 + b3diff

__global__ void prep_kernel(
    const float* __restrict__ w1, const float* __restrict__ b1,
    const float* __restrict__ g1, const float* __restrict__ be1,
    const float* __restrict__ m1, const float* __restrict__ v1,
    const float* __restrict__ w2, const float* __restrict__ b2,
    const float* __restrict__ g2, const float* __restrict__ be2,
    const float* __restrict__ m2, const float* __restrict__ v2,
    const float* __restrict__ w3, const float* __restrict__ b3)
{
    __shared__ float a1[128], c1[128];
    int t = threadIdx.x;  // 128 threads
    {
        float a = g1[t] * rsqrtf(v1[t] + EPS);
        a1[t] = a; c1[t] = be1[t] - a * m1[t];
        g_b1[t] = b1[t];
        #pragma unroll
        for (int n = 0; n < 4; n++) g_w1p[t * 4 + n] = w1[t * 4 + n];
    }
    __syncthreads();
    for (int i = t; i < 128 * 64; i += 128) {
        int j = i >> 7, k = i & 127;
        g_M[k * 64 + j] = w2[j * 128 + k] * a1[k];
    }
    if (t < 64) {
        float acc = b2[t];
        #pragma unroll 8
        for (int k = 0; k < 128; k++) acc += w2[t * 128 + k] * c1[k];
        g_q[t] = acc;
        float a2 = g2[t] * rsqrtf(v2[t] + EPS);
        g_e[t] = (w3[64 + t] - w3[t]) * a2;
    }
    if (t == 0) {
        float C = b3[1] - b3[0];
        for (int j = 0; j < 64; j++) {
            float a2 = g2[j] * rsqrtf(v2[j] + EPS);
            float c2 = be2[j] - a2 * m2[j];
            C += (w3[64 + j] - w3[j]) * c2;
        }
        g_C[0] = C;
    }
}

__device__ __forceinline__ float tanh_approx(float v) {
    float r;
    asm("tanh.approx.f32 %0, %1;" : "=f"(r) : "f"(v));
    return r;
}

// ================= Kernel 1: pure streaming (attention + pooled) =================
__global__ __launch_bounds__(256, 3) void stream_kernel(
    const float* __restrict__ x, const float* __restrict__ mask,
    const float* __restrict__ attn_w, const float* __restrict__ attn_b,
    float* __restrict__ out, int B, int write_weight)
{
    __shared__ float4 s_aw[64];
    __shared__ float s_ab;
    const int tid = threadIdx.x;
    for (int i = tid; i < 64; i += 256) s_aw[i] = ((const float4*)attn_w)[i];
    if (tid == 0) s_ab = attn_b[0];
    __syncthreads();

    const int lane = tid & 31;
    const unsigned FULL = 0xFFFFFFFFu;
    const float4 wa = s_aw[lane], wb = s_aw[32 + lane];
    const float ab = s_ab;

    const int gwarp = blockIdx.x * 8 + (tid >> 5);
    const int totW = gridDim.x * 8;

    for (long long b = gwarp; b < B; b += totW) {
        const float4 mk = __ldg(((const float4*)mask) + b);   // issued early
        const float4* xr = (const float4*)(x + b * 1024);
        float4 xa0 = xr[lane],       xb0 = xr[32 + lane];
        float4 xa1 = xr[64 + lane],  xb1 = xr[96 + lane];
        float4 xa2 = xr[128 + lane], xb2 = xr[160 + lane];
        float4 xa3 = xr[192 + lane], xb3 = xr[224 + lane];

        float s0 = xa0.x*wa.x + xa0.y*wa.y + xa0.z*wa.z + xa0.w*wa.w
                 + xb0.x*wb.x + xb0.y*wb.y + xb0.z*wb.z + xb0.w*wb.w;
        float s1 = xa1.x*wa.x + xa1.y*wa.y + xa1.z*wa.z + xa1.w*wa.w
                 + xb1.x*wb.x + xb1.y*wb.y + xb1.z*wb.z + xb1.w*wb.w;
        float s2 = xa2.x*wa.x + xa2.y*wa.y + xa2.z*wa.z + xa2.w*wa.w
                 + xb2.x*wb.x + xb2.y*wb.y + xb2.z*wb.z + xb2.w*wb.w;
        float s3 = xa3.x*wa.x + xa3.y*wa.y + xa3.z*wa.z + xa3.w*wa.w
                 + xb3.x*wb.x + xb3.y*wb.y + xb3.z*wb.z + xb3.w*wb.w;
        #pragma unroll
        for (int o = 16; o; o >>= 1) {
            s0 += __shfl_xor_sync(FULL, s0, o);
            s1 += __shfl_xor_sync(FULL, s1, o);
            s2 += __shfl_xor_sync(FULL, s2, o);
            s3 += __shfl_xor_sync(FULL, s3, o);
        }

        float t0 = tanh_approx(s0 + ab) + mk.x;
        float t1 = tanh_approx(s1 + ab) + mk.y;
        float t2 = tanh_approx(s2 + ab) + mk.z;
        float t3 = tanh_approx(s3 + ab) + mk.w;

        float mx = fmaxf(fmaxf(t0, t1), fmaxf(t2, t3));
        float e0 = __expf(t0 - mx), e1 = __expf(t1 - mx);
        float e2 = __expf(t2 - mx), e3 = __expf(t3 - mx);
        float inv = 1.0f / (e0 + e1 + e2 + e3);
        float wt0 = e0 * inv, wt1 = e1 * inv, wt2 = e2 * inv, wt3 = e3 * inv;

        float4 pa, pb;
        pa.x = wt0*xa0.x + wt1*xa1.x + wt2*xa2.x + wt3*xa3.x;
        pa.y = wt0*xa0.y + wt1*xa1.y + wt2*xa2.y + wt3*xa3.y;
        pa.z = wt0*xa0.z + wt1*xa1.z + wt2*xa2.z + wt3*xa3.z;
        pa.w = wt0*xa0.w + wt1*xa1.w + wt2*xa2.w + wt3*xa3.w;
        pb.x = wt0*xb0.x + wt1*xb1.x + wt2*xb2.x + wt3*xb3.x;
        pb.y = wt0*xb0.y + wt1*xb1.y + wt2*xb2.y + wt3*xb3.y;
        pb.z = wt0*xb0.z + wt1*xb1.z + wt2*xb2.z + wt3*xb3.z;
        pb.w = wt0*xb0.w + wt1*xb1.w + wt2*xb2.w + wt3*xb3.w;

        float4* orow = (float4*)(out + (size_t)b * 256);
        orow[lane]      = pa;
        orow[32 + lane] = pb;

        if (lane == 0) {
            float4 wv = make_float4(wt0, wt1, wt2, wt3);
            g_wt[b] = wv;
            if (write_weight)
                *(float4*)(out + (size_t)B * 256 + (size_t)b * 4) = wv;
        }
    }
}

__device__ __forceinline__ unsigned long long ffma2(
    unsigned long long a, unsigned long long b, unsigned long long c)
{
    unsigned long long d;
    asm("fma.rn.f32x2 %0, %1, %2, %3;" : "=l"(d) : "l"(a), "l"(b), "l"(c));
    return d;
}

// ================= Kernel 2: classifier MLP + rare gather overwrite =================
__global__ __launch_bounds__(256) void mlp_kernel(
    const float* __restrict__ x, float* __restrict__ out,
    int B, int write_cls)
{
    __shared__ float4 s_M4[128 * 16];   // 32KB
    __shared__ float4 s_w1p[128];
    __shared__ float  s_b1[128];
    __shared__ float  s_q[64], s_e[64];
    __shared__ float  s_C;

    const int tid = threadIdx.x;
    for (int i = tid; i < 2048; i += 256) s_M4[i] = ((const float4*)g_M)[i];
    for (int i = tid; i < 128; i += 256) {
        s_w1p[i] = ((const float4*)g_w1p)[i];
        s_b1[i] = g_b1[i];
    }
    for (int i = tid; i < 64; i += 256) { s_q[i] = g_q[i]; s_e[i] = g_e[i]; }
    if (tid == 0) s_C = g_C[0];
    __syncthreads();

    const int lane = tid & 31;
    const unsigned FULL = 0xFFFFFFFFu;
    const float Cc = s_C;
    const int nGroups = (B + 31) >> 5;
    const int gwarp = blockIdx.x * 8 + (tid >> 5);
    const int totW = gridDim.x * 8;

    for (int g = gwarp; g < nGroups; g += totW) {
        const long long base = (long long)g << 5;
        const int rmax = (int)min((long long)32, (long long)B - base);
        const bool myvalid = (lane < rmax);

        float4 wt = myvalid ? g_wt[base + lane] : make_float4(1.f, 0.f, 0.f, 0.f);

        // argmax of stored weights (== reference argmax(weight), first occurrence)
        int mmi = 0; float bm = wt.x;
        if (wt.y > bm) { bm = wt.y; mmi = 1; }
        if (wt.z > bm) { bm = wt.z; mmi = 2; }
        if (wt.w > bm) { bm = wt.w; mmi = 3; }

        unsigned long long acc[32];
        #pragma unroll
        for (int i = 0; i < 32; i++) acc[i] = 0ull;

        const ulonglong2* Mp = (const ulonglong2*)s_M4;
        #pragma unroll 4
        for (int k = 0; k < 128; k++) {
            float4 wp = s_w1p[k];
            float z = fmaf(wt.x, wp.x, fmaf(wt.y, wp.y,
                      fmaf(wt.z, wp.z, fmaf(wt.w, wp.w, s_b1[k]))));
            float v = fmaxf(z, 0.0f);
            unsigned long long vv;
            asm("mov.b64 %0, {%1, %1};" : "=l"(vv) : "f"(v));
            const ulonglong2* row = Mp + k * 16;
            #pragma unroll
            for (int t = 0; t < 16; t++) {
                ulonglong2 m = row[t];
                acc[2 * t]     = ffma2(m.x, vv, acc[2 * t]);
                acc[2 * t + 1] = ffma2(m.y, vv, acc[2 * t + 1]);
            }
        }

        float dec = Cc;
        #pragma unroll
        for (int i = 0; i < 32; i++) {
            float z0 = __uint_as_float((unsigned)(acc[i] & 0xFFFFFFFFull)) + s_q[2 * i];
            float z1 = __uint_as_float((unsigned)(acc[i] >> 32))           + s_q[2 * i + 1];
            dec = fmaf(s_e[2 * i],     fmaxf(z0, 0.0f), dec);
            dec = fmaf(s_e[2 * i + 1], fmaxf(z1, 0.0f), dec);
        }
        const bool cls1 = myvalid && (dec > LN3);

        // rare overwrite with argmax-gathered member
        unsigned mbits = __ballot_sync(FULL, cls1);
        while (mbits) {
            const int r = __ffs(mbits) - 1;
            mbits &= mbits - 1;
            const long long b = base + r;
            const int gmi = __shfl_sync(FULL, mmi, r);
            const float4* gsrc = (const float4*)(x + b * 1024 + (size_t)gmi * 256);
            float4 v0 = gsrc[lane], v1 = gsrc[32 + lane];
            float4* orow = (float4*)(out + (size_t)b * 256);
            orow[lane]      = v0;
            orow[32 + lane] = v1;
        }
        if (write_cls && myvalid)
            out[(size_t)B * 260 + base + lane] = cls1 ? 1.0f : 0.0f;
    }
}

extern "C" void kernel_launch(void* const* d_in, const int* in_sizes, int n_in,
                              void* d_out, int out_size)
{
    const float* x      = (const float*)d_in[0];
    const float* mask   = (const float*)d_in[1];
    const float* attn_w = (const float*)d_in[2];
    const float* attn_b = (const float*)d_in[3];
    const float* w1     = (const float*)d_in[4];
    const float* b1     = (const float*)d_in[5];
    const float* g1     = (const float*)d_in[6];
    const float* be1    = (const float*)d_in[7];
    const float* m1     = (const float*)d_in[8];
    const float* v1     = (const float*)d_in[9];
    const float* w2     = (const float*)d_in[10];
    const float* b2     = (const float*)d_in[11];
    const float* g2     = (const float*)d_in[12];
    const float* be2    = (const float*)d_in[13];
    const float* m2     = (const float*)d_in[14];
    const float* v2     = (const float*)d_in[15];
    const float* w3     = (const float*)d_in[16];
    const float* b3     = (const float*)d_in[17];
    float* out = (float*)d_out;

    const int B = in_sizes[0] / 1024;   // x = [B,4,256]
    const long long need_w = (long long)B * 260;
    const long long need_c = (long long)B * 261;
    const int write_weight = ((long long)out_size >= need_w) ? 1 : 0;
    const int write_cls    = ((long long)out_size >= need_c) ? 1 : 0;

    prep_kernel<<<1, 128>>>(w1, b1, g1, be1, m1, v1,
                            w2, b2, g2, be2, m2, v2, w3, b3);
    stream_kernel<<<2048, 256>>>(x, mask, attn_w, attn_b, out, B, write_weight);
    mlp_kernel<<<2048, 256>>>(x, out, B, write_cls);
}